// round 8
// baseline (speedup 1.0000x reference)
#include <cuda_runtime.h>
#include <stdint.h>

// Shapes:
//   core0: (1, 50, 8, 16)   -> A[v0][e0][r1]   (A tile per v0 = 128 floats)
//   core1: (16, 50, 4, 16)  -> B[r1][v1][e1][r2]
//   core2: (16, 80, 4, 1)   -> C[r2][v2][e2]
//   indices: 8192, vocab 200000 = (50,50,80) row-major
//   out: (8192, 128) fp32, embed index = e0*16 + e1*4 + e2

#define NV1 50
#define NV2 80
#define RANK 16
#define NIDX 8192
#define NPAIRS (NV1 * NV2)          // 4000
#define HBLOCKS (NPAIRS / 8)        // 500
#define PBLOCKS (NIDX / 256)        // 32

// H[(v1*80+v2)][r1][e1*4+e2]: 4 MB, L2-resident
__device__ float g_H[NPAIRS * RANK * 16];
// packed per-index decomposition: pv = (v0 << 12) | (v1*80+v2)
__device__ int g_pv[NIDX];

__device__ __forceinline__ void cpasync16(uint32_t dst, const void* src) {
    asm volatile("cp.async.cg.shared.global [%0], [%1], 16;" :: "r"(dst), "l"(src) : "memory");
}

// ---------------------------------------------------------------------------
// Kernel 1: blocks [0,500): build H (8 pairs/block, all sharing v1).
//           blocks [500,532): decompose indices into g_pv.
// ---------------------------------------------------------------------------
__global__ __launch_bounds__(256) void tt_build_H(
    const float* __restrict__ core1,   // (16,50,4,16)
    const float* __restrict__ core2,   // (16,80,4,1)
    const void*  __restrict__ idx_raw)
{
    const int tid  = threadIdx.x;
    const int lane = tid & 31;

    if (blockIdx.x >= HBLOCKS) {
        // ---- index prep: one thread per index -----------------------------
        const int i = (blockIdx.x - HBLOCKS) * 256 + tid;
        const int* i32 = (const int*)idx_raw;
        const bool is64 = __all_sync(0xffffffffu, i32[2 * lane + 1] == 0);
        const int iv = is64 ? (int)((const long long*)idx_raw)[i] : i32[i];
        const int v0 = iv / NPAIRS;
        const int p  = iv - v0 * NPAIRS;
        g_pv[i] = (v0 << 12) | p;
        return;
    }

    // ---- H build ----------------------------------------------------------
    __shared__ __align__(16) float sB[16 * 68];  // B[:,v1], padded chunks
    __shared__ __align__(16) float4 sc[8][16];   // per-warp C slice

    const int w     = tid >> 5;
    const int pair0 = blockIdx.x * 8;            // 8 consecutive pairs, same v1
    const int v1    = pair0 / NV2;
    const int v2    = (pair0 - v1 * NV2) + w;

    {
        const int r1 = tid >> 4;
        const int c4 = tid & 15;
        const float4 b = __ldg((const float4*)(core1 + ((size_t)r1 * NV1 + v1) * 64) + c4);
        *(float4*)&sB[r1 * 68 + c4 * 4] = b;
    }
    if (lane < RANK)
        sc[w][lane] = __ldg((const float4*)(core2 + ((size_t)lane * NV2 + v2) * 4));
    __syncthreads();

    float* hout = g_H + (size_t)(v1 * NV2 + v2) * (RANK * 16);

#pragma unroll
    for (int pass = 0; pass < 2; ++pass) {
        const int j  = lane + 32 * pass;
        const int r1 = j >> 2;
        const int e1 = j & 3;

        const float* bp = &sB[r1 * 68 + e1 * 16];
        const float4 b0 = *(const float4*)(bp + 0);
        const float4 b1 = *(const float4*)(bp + 4);
        const float4 b2 = *(const float4*)(bp + 8);
        const float4 b3 = *(const float4*)(bp + 12);
        const float bb[RANK] = { b0.x, b0.y, b0.z, b0.w,  b1.x, b1.y, b1.z, b1.w,
                                 b2.x, b2.y, b2.z, b2.w,  b3.x, b3.y, b3.z, b3.w };

        float4 acc = make_float4(0.f, 0.f, 0.f, 0.f);
#pragma unroll
        for (int r2 = 0; r2 < RANK; ++r2) {
            const float4 c4 = sc[w][r2];
            acc.x = fmaf(bb[r2], c4.x, acc.x);
            acc.y = fmaf(bb[r2], c4.y, acc.y);
            acc.z = fmaf(bb[r2], c4.z, acc.z);
            acc.w = fmaf(bb[r2], c4.w, acc.w);
        }
        ((float4*)hout)[j] = acc;
    }
}

// ---------------------------------------------------------------------------
// Kernel 2: warp = 2 indices. 6 cp.async 16B copies per lane stage A+H tiles
// into smem with ZERO register cost, then broadcast-LDS compute.
//   Lane l: e0=l>>2, q=l&3 owns out[l*4 .. l*4+3] of each row.
// ---------------------------------------------------------------------------
__global__ __launch_bounds__(256) void tt_gather(
    const float* __restrict__ core0,   // (1,50,8,16)
    float* __restrict__ out)           // (8192,128)
{
    // Per-warp f4 layout: [0..31]=A0 [32..95]=H0 [96..127]=A1 [128..191]=H1
    __shared__ __align__(16) float4 sh[8][192];

    const int w    = threadIdx.x >> 5;
    const int lane = threadIdx.x & 31;
    const int warp = blockIdx.x * 8 + w;
    const int i0   = warp * 2;
    const int i1   = i0 + 1;

    const int pv0 = __ldg(&g_pv[i0]);            // broadcast 4B loads
    const int pv1 = __ldg(&g_pv[i1]);

    const float4* At0 = (const float4*)core0 + (size_t)(pv0 >> 12) * 32;
    const float4* Ht0 = (const float4*)g_H   + (size_t)(pv0 & 4095) * 64;
    const float4* At1 = (const float4*)core0 + (size_t)(pv1 >> 12) * 32;
    const float4* Ht1 = (const float4*)g_H   + (size_t)(pv1 & 4095) * 64;

    // 6 in-flight 16B copies, no destination registers.
    const uint32_t sbase = (uint32_t)__cvta_generic_to_shared(&sh[w][0]);
    cpasync16(sbase + (lane)        * 16, At0 + lane);
    cpasync16(sbase + (32  + lane)  * 16, Ht0 + lane);
    cpasync16(sbase + (64  + lane)  * 16, Ht0 + lane + 32);
    cpasync16(sbase + (96  + lane)  * 16, At1 + lane);
    cpasync16(sbase + (128 + lane)  * 16, Ht1 + lane);
    cpasync16(sbase + (160 + lane)  * 16, Ht1 + lane + 32);
    asm volatile("cp.async.commit_group;" ::: "memory");
    asm volatile("cp.async.wait_group 0;"  ::: "memory");
    __syncwarp();

    const int e0 = lane >> 2;
    const int q  = lane & 3;

#pragma unroll
    for (int t = 0; t < 2; ++t) {
        const int abase = t ? 96 : 0;
        const int hbase = t ? 128 : 32;

        float a[RANK];
#pragma unroll
        for (int k = 0; k < 4; ++k) {
            const float4 t4 = sh[w][abase + e0 * 4 + k];
            a[4 * k + 0] = t4.x; a[4 * k + 1] = t4.y; a[4 * k + 2] = t4.z; a[4 * k + 3] = t4.w;
        }

        float4 acc = make_float4(0.f, 0.f, 0.f, 0.f);
#pragma unroll
        for (int r1 = 0; r1 < RANK; ++r1) {
            const float4 h = sh[w][hbase + r1 * 4 + q];
            acc.x = fmaf(a[r1], h.x, acc.x);
            acc.y = fmaf(a[r1], h.y, acc.y);
            acc.z = fmaf(a[r1], h.z, acc.z);
            acc.w = fmaf(a[r1], h.w, acc.w);
        }

        ((float4*)(out + (size_t)(t ? i1 : i0) * 128))[lane] = acc;
    }
}

// Inputs (metadata order): indices, core0, core1, core2
extern "C" void kernel_launch(void* const* d_in, const int* in_sizes, int n_in,
                              void* d_out, int out_size)
{
    const void*  indices = d_in[0];
    const float* core0   = (const float*)d_in[1];
    const float* core1   = (const float*)d_in[2];
    const float* core2   = (const float*)d_in[3];
    float* out = (float*)d_out;

    tt_build_H<<<HBLOCKS + PBLOCKS, 256>>>(core1, core2, indices);
    tt_gather<<<NIDX / 16, 256>>>(core0, out);
}